// round 14
// baseline (speedup 1.0000x reference)
#include <cuda_runtime.h>
#include <cuda_bf16.h>
#include <stdint.h>

#define N_ROWS 65536
#define DIN    512
#define H      128
#define D      32
#define KCB    1024
#define BN_EPS 1e-5f

// ---------------- scratch ----------------------------------------------------
__device__ __nv_bfloat16 g_h1b[(size_t)N_ROWS * H];
__device__ __nv_bfloat16 g_zb[(size_t)N_ROWS * D];
__device__ uint2    g_w1frag[32 * 16 * 32];   // [kc][ntile][lane] b0,b1 words
__device__ float    g_znorm[N_ROWS];
__device__ int      g_topics[N_ROWS];
__device__ float    g_colsum[H];
__device__ float    g_colsumsq[H];
__device__ int      g_counts[KCB];
__device__ uint32_t g_cbb[KCB * 16];
__device__ float    g_cnorm[KCB];
__device__ float    g_proj[KCB * H];
__device__ float    g_dsum[H];
__device__ float    g_dss[H];
__device__ float    g_xrow[KCB * DIN];
__device__ double   g_zcloss;
__device__ double   g_recon;

__device__ __forceinline__ uint32_t packbf(float lo, float hi) {
    uint32_t r;
    asm("cvt.rn.bf16x2.f32 %0, %1, %2;" : "=r"(r) : "f"(hi), "f"(lo));
    return r;
}

__device__ __forceinline__ void mma16816(float& d0, float& d1, float& d2, float& d3,
                                         uint32_t a0, uint32_t a1, uint32_t a2, uint32_t a3,
                                         uint32_t b0, uint32_t b1) {
    asm volatile(
        "mma.sync.aligned.m16n8k16.row.col.f32.bf16.bf16.f32 "
        "{%0,%1,%2,%3}, {%4,%5,%6,%7}, {%8,%9}, {%0,%1,%2,%3};"
        : "+f"(d0), "+f"(d1), "+f"(d2), "+f"(d3)
        : "r"(a0), "r"(a1), "r"(a2), "r"(a3), "r"(b0), "r"(b1));
}

// ---------------- prep kernels (merged so k_gemm2 is launch #4) --------------
__global__ void k_zero_a() {
    int i = blockIdx.x * 256 + threadIdx.x;
    if (i < H) { g_colsum[i] = 0.f; g_colsumsq[i] = 0.f; g_dsum[i] = 0.f; g_dss[i] = 0.f; }
    if (i < KCB) g_counts[i] = 0;
    if (i == 0) { g_zcloss = 0.0; g_recon = 0.0; }
}

__global__ void k_zero_bc(const float* __restrict__ CB, const float* __restrict__ W1) {
    const int gi = blockIdx.x * 256 + threadIdx.x;   // 0..2047
    if (gi < KCB) {
        const int i = gi;                            // codeword
        const float4* src = reinterpret_cast<const float4*>(CB + i * D);
        uint32_t w[16];
        float nrm = 0.f;
#pragma unroll
        for (int q = 0; q < 8; q++) {
            float4 v = src[q];
            uint32_t p0 = packbf(v.x, v.y);
            uint32_t p1 = packbf(v.z, v.w);
            w[q * 2] = p0; w[q * 2 + 1] = p1;
            __nv_bfloat162 h0 = *reinterpret_cast<__nv_bfloat162*>(&p0);
            __nv_bfloat162 h1 = *reinterpret_cast<__nv_bfloat162*>(&p1);
            float2 f0 = __bfloat1622float2(h0), f1 = __bfloat1622float2(h1);
            nrm += f0.x * f0.x + f0.y * f0.y + f1.x * f1.x + f1.y * f1.y;
        }
        uint4* dst = reinterpret_cast<uint4*>(g_cbb + i * 16);
#pragma unroll
        for (int q = 0; q < 4; q++)
            dst[q] = make_uint4(w[q * 4], w[q * 4 + 1], w[q * 4 + 2], w[q * 4 + 3]);
        g_cnorm[i] = nrm;
    } else {
        const int tid = gi - KCB;                    // 0..1023, w1 fragments
#pragma unroll
        for (int e = 0; e < 16; e++) {
            int idx = tid * 16 + e;
            int l   = idx & 31;
            int nt  = (idx >> 5) & 15;
            int kc  = idx >> 9;
            int n   = nt * 8 + (l >> 2);
            int k   = kc * 16 + (l & 3) * 2;
            float w00 = W1[(size_t)k * H + n];
            float w01 = W1[(size_t)(k + 1) * H + n];
            float w10 = W1[(size_t)(k + 8) * H + n];
            float w11 = W1[(size_t)(k + 9) * H + n];
            g_w1frag[idx] = make_uint2(packbf(w00, w01), packbf(w10, w11));
        }
    }
}

// ---------------- GEMM1 v4: hybrid + column-split warps ----------------------
// block = 512 threads / 16 warps; warp = 16 rows x 64 cols; grid 512.
__global__ void __launch_bounds__(512, 2) k_gemm1(const float* __restrict__ X) {
    __shared__ uint2 bsm[2][512];           // [buf][nt*32+lane], 4KB each
    __shared__ float ssum[H], ssq[H];
    const int tid  = threadIdx.x;
    const int w    = tid >> 5;
    const int lane = tid & 31;
    const int qrow = lane >> 2;
    const int qp   = lane & 3;
    const int wm   = w >> 1;                // 0..7 (row group)
    const int wn   = w & 1;                 // 0..1 (col half)
    const int r0   = blockIdx.x * 128 + wm * 16;

    if (tid < H) { ssum[tid] = 0.f; ssq[tid] = 0.f; }
    {   // prologue: B slice kc=0 -> buf0 (one uint2 per thread, coalesced)
        bsm[0][tid] = g_w1frag[tid];
    }
    __syncthreads();

    const float2* xrow0 = reinterpret_cast<const float2*>(X + (size_t)(r0 + qrow) * DIN);
    const float2* xrow1 = reinterpret_cast<const float2*>(X + (size_t)(r0 + qrow + 8) * DIN);

    float acc[8][4];
#pragma unroll
    for (int j = 0; j < 8; j++)
#pragma unroll
        for (int q = 0; q < 4; q++) acc[j][q] = 0.f;

    uint2 pf;
    for (int kc = 0; kc < 32; kc++) {
        const int buf = kc & 1;
        const bool has_next = (kc + 1 < 32);
        if (has_next)
            pf = g_w1frag[(kc + 1) * 512 + tid];

        // A fragments straight from X (fp32 -> bf16 in regs)
        float2 x0 = xrow0[kc * 8 + qp];
        float2 x1 = xrow1[kc * 8 + qp];
        float2 x2 = xrow0[kc * 8 + qp + 4];
        float2 x3 = xrow1[kc * 8 + qp + 4];
        uint32_t a0 = packbf(x0.x, x0.y);
        uint32_t a1 = packbf(x1.x, x1.y);
        uint32_t a2 = packbf(x2.x, x2.y);
        uint32_t a3 = packbf(x3.x, x3.y);

        const uint2* bb = &bsm[buf][wn * 256 + lane];   // nt = wn*8 + j
#pragma unroll
        for (int j = 0; j < 8; j++) {
            uint2 b = bb[j * 32];
            mma16816(acc[j][0], acc[j][1], acc[j][2], acc[j][3],
                     a0, a1, a2, a3, b.x, b.y);
        }
        if (has_next)
            bsm[buf ^ 1][tid] = pf;
        __syncthreads();
    }

    // write h1 bf16 directly from accumulators (warp covers cols wn*64..+63)
    uint32_t* out0 = reinterpret_cast<uint32_t*>(g_h1b) + (size_t)(r0 + qrow) * 64;
    uint32_t* out1 = reinterpret_cast<uint32_t*>(g_h1b) + (size_t)(r0 + qrow + 8) * 64;
#pragma unroll
    for (int j = 0; j < 8; j++) {
        int nt = wn * 8 + j;
        out0[nt * 4 + qp] = packbf(acc[j][0], acc[j][1]);
        out1[nt * 4 + qp] = packbf(acc[j][2], acc[j][3]);
    }

    // BN column sums from accumulators (reduce 8 qrow lanes, stride 4)
#pragma unroll
    for (int j = 0; j < 8; j++) {
        int nt = wn * 8 + j;
        float s0 = acc[j][0] + acc[j][2];
        float s1 = acc[j][1] + acc[j][3];
        float q0 = acc[j][0] * acc[j][0] + acc[j][2] * acc[j][2];
        float q1 = acc[j][1] * acc[j][1] + acc[j][3] * acc[j][3];
#pragma unroll
        for (int off = 16; off >= 4; off >>= 1) {
            s0 += __shfl_down_sync(0xffffffffu, s0, off);
            s1 += __shfl_down_sync(0xffffffffu, s1, off);
            q0 += __shfl_down_sync(0xffffffffu, q0, off);
            q1 += __shfl_down_sync(0xffffffffu, q1, off);
        }
        if (lane < 4) {
            int c = nt * 8 + lane * 2;
            atomicAdd(&ssum[c],     s0);
            atomicAdd(&ssum[c + 1], s1);
            atomicAdd(&ssq[c],      q0);
            atomicAdd(&ssq[c + 1],  q1);
        }
    }
    __syncthreads();
    if (tid < H) {
        atomicAdd(&g_colsum[tid],   ssum[tid]);
        atomicAdd(&g_colsumsq[tid], ssq[tid]);
    }
}

// ---------------- GEMM2: z = relu(bn(h1)) @ enc_w2 + b2 ----------------------
__global__ void __launch_bounds__(256) k_gemm2(const float* __restrict__ g1,
                                               const float* __restrict__ be1,
                                               const float* __restrict__ W2,
                                               const float* __restrict__ B2) {
    __shared__ float As[32][129];
    __shared__ float Ws2[H * D];
    __shared__ float sc[H], sh[H];
    const int tid  = threadIdx.x;
    const int row0 = blockIdx.x * 32;

    if (tid < H) {
        float mu  = g_colsum[tid] * (1.0f / N_ROWS);
        float var = g_colsumsq[tid] * (1.0f / N_ROWS) - mu * mu;
        float s   = g1[tid] * rsqrtf(var + BN_EPS);
        sc[tid] = s;
        sh[tid] = be1[tid] - mu * s;
    }
    for (int i = tid; i < H * D; i += 256) Ws2[i] = W2[i];
    __syncthreads();

    const uint4* src = reinterpret_cast<const uint4*>(g_h1b + (size_t)row0 * H);
    for (int u = tid; u < 512; u += 256) {
        uint4 v = src[u];
        int r = u >> 4, c0 = (u & 15) * 8;
        const __nv_bfloat162* hp = reinterpret_cast<const __nv_bfloat162*>(&v);
#pragma unroll
        for (int q = 0; q < 4; q++) {
            float2 f = __bfloat1622float2(hp[q]);
            int c = c0 + q * 2;
            As[r][c]     = fmaxf(fmaf(f.x, sc[c],     sh[c]),     0.f);
            As[r][c + 1] = fmaxf(fmaf(f.y, sc[c + 1], sh[c + 1]), 0.f);
        }
    }
    __syncthreads();

    const int r  = tid >> 3;
    const int c0 = (tid & 7) * 4;
    float a0 = B2[c0], a1 = B2[c0 + 1], a2 = B2[c0 + 2], a3 = B2[c0 + 3];
#pragma unroll 4
    for (int k = 0; k < H; k++) {
        float a = As[r][k];
        const float4 wvv = *reinterpret_cast<const float4*>(&Ws2[k * D + c0]);
        a0 = fmaf(a, wvv.x, a0); a1 = fmaf(a, wvv.y, a1);
        a2 = fmaf(a, wvv.z, a2); a3 = fmaf(a, wvv.w, a3);
    }
    uint32_t u0 = packbf(a0, a1), u1 = packbf(a2, a3);
    *reinterpret_cast<uint2*>(g_zb + (size_t)(row0 + r) * D + c0) = make_uint2(u0, u1);

    __nv_bfloat162 h0 = *reinterpret_cast<__nv_bfloat162*>(&u0);
    __nv_bfloat162 h1 = *reinterpret_cast<__nv_bfloat162*>(&u1);
    float2 f0 = __bfloat1622float2(h0), f1 = __bfloat1622float2(h1);
    float part = f0.x * f0.x + f0.y * f0.y + f1.x * f1.x + f1.y * f1.y;
#pragma unroll
    for (int o = 1; o <= 4; o <<= 1) part += __shfl_xor_sync(0xffffffffu, part, o);
    if ((tid & 7) == 0) g_znorm[row0 + r] = part;
}

// ---------------- assign: MMA distances + packed-uint argmin -----------------
__global__ void __launch_bounds__(256) k_assign() {
    extern __shared__ char smraw[];
    uint32_t* cbw = reinterpret_cast<uint32_t*>(smraw);           // [1024*16] swizzled
    float2*  cnorm2 = reinterpret_cast<float2*>(smraw + KCB * 64);

    const int tid  = threadIdx.x;
    const int row0 = blockIdx.x * 256;

    for (int wb = tid * 4; wb < KCB * 16; wb += 256 * 4) {
        uint4 v = *reinterpret_cast<const uint4*>(g_cbb + wb);
        int r = wb >> 4, w0 = wb & 15;
        int base = r << 4, sw = r & 7;
        cbw[base | ((w0 + 0) ^ sw)] = v.x;
        cbw[base | ((w0 + 1) ^ sw)] = v.y;
        cbw[base | ((w0 + 2) ^ sw)] = v.z;
        cbw[base | ((w0 + 3) ^ sw)] = v.w;
    }
    {
        float4 v = reinterpret_cast<const float4*>(g_cnorm)[tid];
        reinterpret_cast<float4*>(cnorm2)[tid] = v;
    }
    __syncthreads();

    const int w    = tid >> 5;
    const int lane = tid & 31;
    const int qrow = lane >> 2;
    const int qp   = lane & 3;

    const int r0 = row0 + w * 32 + qrow;
    const uint32_t* zw = reinterpret_cast<const uint32_t*>(g_zb);
    uint32_t a00 = zw[(size_t)(r0     ) * 16 + qp];
    uint32_t a01 = zw[(size_t)(r0 +  8) * 16 + qp];
    uint32_t a02 = zw[(size_t)(r0     ) * 16 + qp + 4];
    uint32_t a03 = zw[(size_t)(r0 +  8) * 16 + qp + 4];
    uint32_t a04 = zw[(size_t)(r0     ) * 16 + qp + 8];
    uint32_t a05 = zw[(size_t)(r0 +  8) * 16 + qp + 8];
    uint32_t a06 = zw[(size_t)(r0     ) * 16 + qp + 12];
    uint32_t a07 = zw[(size_t)(r0 +  8) * 16 + qp + 12];
    uint32_t a10 = zw[(size_t)(r0 + 16) * 16 + qp];
    uint32_t a11 = zw[(size_t)(r0 + 24) * 16 + qp];
    uint32_t a12 = zw[(size_t)(r0 + 16) * 16 + qp + 4];
    uint32_t a13 = zw[(size_t)(r0 + 24) * 16 + qp + 4];
    uint32_t a14 = zw[(size_t)(r0 + 16) * 16 + qp + 8];
    uint32_t a15 = zw[(size_t)(r0 + 24) * 16 + qp + 8];
    uint32_t a16 = zw[(size_t)(r0 + 16) * 16 + qp + 12];
    uint32_t a17 = zw[(size_t)(r0 + 24) * 16 + qp + 12];

    const float zn0 = g_znorm[r0];
    const float zn1 = g_znorm[r0 + 8];
    const float zn2 = g_znorm[r0 + 16];
    const float zn3 = g_znorm[r0 + 24];

    uint32_t best0 = 0xFFFFFFFFu, best1 = 0xFFFFFFFFu;
    uint32_t best2 = 0xFFFFFFFFu, best3 = 0xFFFFFFFFu;
    const int boff = (qrow << 4) | (qp ^ qrow);

#pragma unroll 2
    for (int nt = 0; nt < KCB / 8; nt++) {
        uint32_t b0 = cbw[nt * 128 + boff];
        uint32_t b1 = cbw[nt * 128 + (boff ^ 4)];
        uint32_t b2 = cbw[nt * 128 + (boff ^ 8)];
        uint32_t b3 = cbw[nt * 128 + (boff ^ 12)];

        float d0 = 0.f, d1 = 0.f, d2 = 0.f, d3 = 0.f;
        float e0 = 0.f, e1 = 0.f, e2 = 0.f, e3 = 0.f;
        mma16816(d0, d1, d2, d3, a00, a01, a02, a03, b0, b1);
        mma16816(d0, d1, d2, d3, a04, a05, a06, a07, b2, b3);
        mma16816(e0, e1, e2, e3, a10, a11, a12, a13, b0, b1);
        mma16816(e0, e1, e2, e3, a14, a15, a16, a17, b2, b3);

        int ncol = nt * 8 + qp * 2;
        float2 cn = cnorm2[nt * 4 + qp];
        uint32_t k00 = (__float_as_uint(fmaf(-2.f, d0, zn0 + cn.x)) & 0xFFFFFC00u) | ncol;
        uint32_t k01 = (__float_as_uint(fmaf(-2.f, d1, zn0 + cn.y)) & 0xFFFFFC00u) | (ncol + 1);
        uint32_t k10 = (__float_as_uint(fmaf(-2.f, d2, zn1 + cn.x)) & 0xFFFFFC00u) | ncol;
        uint32_t k11 = (__float_as_uint(fmaf(-2.f, d3, zn1 + cn.y)) & 0xFFFFFC00u) | (ncol + 1);
        uint32_t k20 = (__float_as_uint(fmaf(-2.f, e0, zn2 + cn.x)) & 0xFFFFFC00u) | ncol;
        uint32_t k21 = (__float_as_uint(fmaf(-2.f, e1, zn2 + cn.y)) & 0xFFFFFC00u) | (ncol + 1);
        uint32_t k30 = (__float_as_uint(fmaf(-2.f, e2, zn3 + cn.x)) & 0xFFFFFC00u) | ncol;
        uint32_t k31 = (__float_as_uint(fmaf(-2.f, e3, zn3 + cn.y)) & 0xFFFFFC00u) | (ncol + 1);
        best0 = min(best0, min(k00, k01));
        best1 = min(best1, min(k10, k11));
        best2 = min(best2, min(k20, k21));
        best3 = min(best3, min(k30, k31));
    }

#pragma unroll
    for (int off = 1; off <= 2; off <<= 1) {
        best0 = min(best0, __shfl_xor_sync(0xffffffffu, best0, off));
        best1 = min(best1, __shfl_xor_sync(0xffffffffu, best1, off));
        best2 = min(best2, __shfl_xor_sync(0xffffffffu, best2, off));
        best3 = min(best3, __shfl_xor_sync(0xffffffffu, best3, off));
    }

    double db = 0.0;
    if (qp == 0) {
        int c0v = best0 & 0x3FF, c1v = best1 & 0x3FF;
        int c2v = best2 & 0x3FF, c3v = best3 & 0x3FF;
        g_topics[r0]      = c0v;
        g_topics[r0 + 8]  = c1v;
        g_topics[r0 + 16] = c2v;
        g_topics[r0 + 24] = c3v;
        atomicAdd(&g_counts[c0v], 1);
        atomicAdd(&g_counts[c1v], 1);
        atomicAdd(&g_counts[c2v], 1);
        atomicAdd(&g_counts[c3v], 1);
        db = (double)__uint_as_float(best0 & 0xFFFFFC00u)
           + (double)__uint_as_float(best1 & 0xFFFFFC00u)
           + (double)__uint_as_float(best2 & 0xFFFFFC00u)
           + (double)__uint_as_float(best3 & 0xFFFFFC00u);
    }
#pragma unroll
    for (int o = 16; o; o >>= 1) db += __shfl_down_sync(0xffffffffu, db, o);
    if (lane == 0) atomicAdd(&g_zcloss, db);
}

// ---------------- decoder proj + fused weighted BN stats ---------------------
__global__ void __launch_bounds__(128) k_decproj(const float* __restrict__ CB,
                                                 const float* __restrict__ W1d) {
    __shared__ float cbs[16 * D];
    __shared__ float w1s[D * H];
    __shared__ float cnt[16];
    const int tid = threadIdx.x;
    const int k0  = blockIdx.x * 16;

    for (int i = tid * 4; i < 16 * D; i += 128 * 4)
        *reinterpret_cast<float4*>(cbs + i) =
            *reinterpret_cast<const float4*>(CB + k0 * D + i);
    for (int i = tid * 4; i < D * H; i += 128 * 4)
        *reinterpret_cast<float4*>(w1s + i) =
            *reinterpret_cast<const float4*>(W1d + i);
    if (tid < 16) cnt[tid] = (float)g_counts[k0 + tid];
    __syncthreads();

    const int h = tid;
    float s = 0.f, ss = 0.f;
#pragma unroll 4
    for (int kk = 0; kk < 16; kk++) {
        float p = 0.f;
#pragma unroll
        for (int d = 0; d < D; d++) p = fmaf(cbs[kk * D + d], w1s[d * H + h], p);
        g_proj[(k0 + kk) * H + h] = p;
        float c = cnt[kk];
        s  = fmaf(c, p, s);
        ss = fmaf(c * p, p, ss);
    }
    atomicAdd(&g_dsum[h], s);
    atomicAdd(&g_dss[h], ss);
}

// ---------------- decoder output ---------------------------------------------
__global__ void __launch_bounds__(256) k_decout(const float* __restrict__ g2,
                                                const float* __restrict__ be2,
                                                const float* __restrict__ W2d,
                                                const float* __restrict__ B2d) {
    __shared__ float hb[4][H];
    __shared__ float sc2[H], sh2[H];
    const int t  = threadIdx.x;
    const int k0 = blockIdx.x * 4;

    if (t < H) {
        float mu  = g_dsum[t] * (1.0f / N_ROWS);
        float var = g_dss[t] * (1.0f / N_ROWS) - mu * mu;
        float s   = g2[t] * rsqrtf(var + BN_EPS);
        sc2[t] = s;
        sh2[t] = be2[t] - mu * s;
    }
    __syncthreads();
    for (int i = t; i < 4 * H; i += 256) {
        int kk = i >> 7, h = i & 127;
        float v = fmaf(g_proj[(k0 + kk) * H + h], sc2[h], sh2[h]);
        hb[kk][h] = fmaxf(v, 0.f);
    }
    __syncthreads();
    for (int o = t; o < DIN; o += 256) {
        float b = B2d[o];
        float s0 = b, s1 = b, s2 = b, s3 = b;
#pragma unroll 4
        for (int h = 0; h < H; h++) {
            float wv = W2d[h * DIN + o];
            s0 = fmaf(hb[0][h], wv, s0);
            s1 = fmaf(hb[1][h], wv, s1);
            s2 = fmaf(hb[2][h], wv, s2);
            s3 = fmaf(hb[3][h], wv, s3);
        }
        g_xrow[(size_t)(k0 + 0) * DIN + o] = s0;
        g_xrow[(size_t)(k0 + 1) * DIN + o] = s1;
        g_xrow[(size_t)(k0 + 2) * DIN + o] = s2;
        g_xrow[(size_t)(k0 + 3) * DIN + o] = s3;
    }
}

// ---------------- recon loss --------------------------------------------------
__global__ void k_recon(const float* __restrict__ X) {
    const int gtid   = blockIdx.x * blockDim.x + threadIdx.x;
    const int gw     = gtid >> 5;
    const int lane   = threadIdx.x & 31;
    const int nwarps = (gridDim.x * blockDim.x) >> 5;
    double dacc = 0.0;
    for (int n = gw; n < N_ROWS; n += nwarps) {
        int tpc = g_topics[n];
        const float4* xr = reinterpret_cast<const float4*>(g_xrow + (size_t)tpc * DIN);
        const float4* xx = reinterpret_cast<const float4*>(X + (size_t)n * DIN);
        float a = 0.f;
#pragma unroll
        for (int q = 0; q < 4; q++) {
            float4 rv = xr[lane + 32 * q];
            float4 xv = xx[lane + 32 * q];
            float e0 = rv.x - xv.x, e1 = rv.y - xv.y;
            float e2 = rv.z - xv.z, e3 = rv.w - xv.w;
            a = fmaf(e0, e0, a); a = fmaf(e1, e1, a);
            a = fmaf(e2, e2, a); a = fmaf(e3, e3, a);
        }
        dacc += (double)a;
    }
#pragma unroll
    for (int o = 16; o; o >>= 1) dacc += __shfl_down_sync(0xffffffffu, dacc, o);
    if (lane == 0) atomicAdd(&g_recon, dacc);
}

__global__ void k_final(float* __restrict__ out) {
    out[0] = (float)(2.0 * g_zcloss + sqrt(g_recon));
}

// ---------------- launch ------------------------------------------------------
extern "C" void kernel_launch(void* const* d_in, const int* in_sizes, int n_in,
                              void* d_out, int out_size) {
    const float* X        = (const float*)d_in[0];
    const float* enc_w1   = (const float*)d_in[1];
    const float* enc_g1   = (const float*)d_in[3];
    const float* enc_be1  = (const float*)d_in[4];
    const float* enc_w2   = (const float*)d_in[5];
    const float* enc_b2   = (const float*)d_in[6];
    const float* dec_w1   = (const float*)d_in[7];
    const float* dec_g1   = (const float*)d_in[9];
    const float* dec_be1  = (const float*)d_in[10];
    const float* dec_w2   = (const float*)d_in[11];
    const float* dec_b2   = (const float*)d_in[12];
    const float* codebook = (const float*)d_in[13];
    float* out = (float*)d_out;

    const int assign_smem = KCB * 64 + KCB * 4;               // 69632
    cudaFuncSetAttribute(k_assign, cudaFuncAttributeMaxDynamicSharedMemorySize, assign_smem);

    k_zero_a <<<4, 256>>>();                                  // launch 1
    k_zero_bc<<<8, 256>>>(codebook, enc_w1);                  // launch 2
    k_gemm1  <<<N_ROWS / 128, 512>>>(X);                      // launch 3
    k_gemm2  <<<N_ROWS / 32, 256>>>(enc_g1, enc_be1, enc_w2, enc_b2);  // launch 4 (ncu)
    k_assign <<<N_ROWS / 256, 256, assign_smem>>>();
    k_decproj<<<KCB / 16, 128>>>(codebook, dec_w1);
    k_decout <<<KCB / 4, 256>>>(dec_g1, dec_be1, dec_w2, dec_b2);
    k_recon  <<<256, 256>>>(X);
    k_final  <<<1, 1>>>(out);
}

// round 17
// speedup vs baseline: 1.7282x; 1.7282x over previous
#include <cuda_runtime.h>
#include <cuda_bf16.h>
#include <stdint.h>

#define N_ROWS 65536
#define DIN    512
#define H      128
#define D      32
#define KCB    1024
#define BN_EPS 1e-5f

// ---------------- scratch ----------------------------------------------------
__device__ __nv_bfloat16 g_h1b[(size_t)N_ROWS * H];
__device__ __nv_bfloat16 g_zb[(size_t)N_ROWS * D];
__device__ uint2    g_w1frag[32 * 16 * 32];   // [kc][ntile][lane]
__device__ uint2    g_w2frag[8 * 4 * 32];     // [kc][ntile][lane]
__device__ float    g_znorm[N_ROWS];
__device__ int      g_topics[N_ROWS];
__device__ float    g_colsum[H];
__device__ float    g_colsumsq[H];
__device__ int      g_counts[KCB];
__device__ uint32_t g_cbb[KCB * 16];
__device__ float    g_cnorm[KCB];
__device__ float    g_proj[KCB * H];
__device__ float    g_dsum[H];
__device__ float    g_dss[H];
__device__ float    g_xrow[KCB * DIN];
__device__ double   g_zcloss;
__device__ double   g_recon;

__device__ __forceinline__ uint32_t packbf(float lo, float hi) {
    uint32_t r;
    asm("cvt.rn.bf16x2.f32 %0, %1, %2;" : "=r"(r) : "f"(hi), "f"(lo));
    return r;
}

__device__ __forceinline__ void mma16816(float& d0, float& d1, float& d2, float& d3,
                                         uint32_t a0, uint32_t a1, uint32_t a2, uint32_t a3,
                                         uint32_t b0, uint32_t b1) {
    asm volatile(
        "mma.sync.aligned.m16n8k16.row.col.f32.bf16.bf16.f32 "
        "{%0,%1,%2,%3}, {%4,%5,%6,%7}, {%8,%9}, {%0,%1,%2,%3};"
        : "+f"(d0), "+f"(d1), "+f"(d2), "+f"(d3)
        : "r"(a0), "r"(a1), "r"(a2), "r"(a3), "r"(b0), "r"(b1));
}

// ---------------- prep kernels -----------------------------------------------
__global__ void k_zero_a(const float* __restrict__ W2) {
    int i = blockIdx.x * 256 + threadIdx.x;   // 0..1023
    if (i < H) { g_colsum[i] = 0.f; g_colsumsq[i] = 0.f; g_dsum[i] = 0.f; g_dss[i] = 0.f; }
    if (i < KCB) g_counts[i] = 0;
    if (i == 0) { g_zcloss = 0.0; g_recon = 0.0; }
    // enc_w2 -> mma B fragments: i = kc*128 + nt*32 + lane
    {
        int l  = i & 31;
        int nt = (i >> 5) & 3;
        int kc = i >> 7;
        int n  = nt * 8 + (l >> 2);
        int k  = kc * 16 + (l & 3) * 2;
        float w00 = W2[(size_t)k * D + n];
        float w01 = W2[(size_t)(k + 1) * D + n];
        float w10 = W2[(size_t)(k + 8) * D + n];
        float w11 = W2[(size_t)(k + 9) * D + n];
        g_w2frag[i] = make_uint2(packbf(w00, w01), packbf(w10, w11));
    }
}

__global__ void k_zero_bc(const float* __restrict__ CB, const float* __restrict__ W1) {
    const int gi = blockIdx.x * 256 + threadIdx.x;   // 0..2047
    if (gi < KCB) {
        const int i = gi;
        const float4* src = reinterpret_cast<const float4*>(CB + i * D);
        uint32_t w[16];
        float nrm = 0.f;
#pragma unroll
        for (int q = 0; q < 8; q++) {
            float4 v = src[q];
            uint32_t p0 = packbf(v.x, v.y);
            uint32_t p1 = packbf(v.z, v.w);
            w[q * 2] = p0; w[q * 2 + 1] = p1;
            __nv_bfloat162 h0 = *reinterpret_cast<__nv_bfloat162*>(&p0);
            __nv_bfloat162 h1 = *reinterpret_cast<__nv_bfloat162*>(&p1);
            float2 f0 = __bfloat1622float2(h0), f1 = __bfloat1622float2(h1);
            nrm += f0.x * f0.x + f0.y * f0.y + f1.x * f1.x + f1.y * f1.y;
        }
        uint4* dst = reinterpret_cast<uint4*>(g_cbb + i * 16);
#pragma unroll
        for (int q = 0; q < 4; q++)
            dst[q] = make_uint4(w[q * 4], w[q * 4 + 1], w[q * 4 + 2], w[q * 4 + 3]);
        g_cnorm[i] = nrm;
    } else {
        const int tid = gi - KCB;
#pragma unroll
        for (int e = 0; e < 16; e++) {
            int idx = tid * 16 + e;
            int l   = idx & 31;
            int nt  = (idx >> 5) & 15;
            int kc  = idx >> 9;
            int n   = nt * 8 + (l >> 2);
            int k   = kc * 16 + (l & 3) * 2;
            float w00 = W1[(size_t)k * H + n];
            float w01 = W1[(size_t)(k + 1) * H + n];
            float w10 = W1[(size_t)(k + 8) * H + n];
            float w11 = W1[(size_t)(k + 9) * H + n];
            g_w1frag[idx] = make_uint2(packbf(w00, w01), packbf(w10, w11));
        }
    }
}

// ---------------- GEMM1: R10 hybrid (known 75.7us) ---------------------------
// warp = 16 rows x 128 cols; block = 8 warps = 128 rows; grid 512.
__global__ void __launch_bounds__(256) k_gemm1(const float* __restrict__ X) {
    __shared__ uint2 bsm[2][512];
    __shared__ float ssum[H], ssq[H];
    const int tid  = threadIdx.x;
    const int w    = tid >> 5;
    const int lane = tid & 31;
    const int qrow = lane >> 2;
    const int qp   = lane & 3;
    const int r0   = blockIdx.x * 128 + w * 16;

    if (tid < H) { ssum[tid] = 0.f; ssq[tid] = 0.f; }
    {
        uint4 v = reinterpret_cast<const uint4*>(g_w1frag)[tid];
        reinterpret_cast<uint4*>(bsm[0])[tid] = v;
    }
    __syncthreads();

    const float2* xrow0 = reinterpret_cast<const float2*>(X + (size_t)(r0 + qrow) * DIN);
    const float2* xrow1 = reinterpret_cast<const float2*>(X + (size_t)(r0 + qrow + 8) * DIN);

    float acc[16][4];
#pragma unroll
    for (int nt = 0; nt < 16; nt++)
#pragma unroll
        for (int j = 0; j < 4; j++) acc[nt][j] = 0.f;

    uint4 pf;
    for (int kc = 0; kc < 32; kc++) {
        const int buf = kc & 1;
        const bool has_next = (kc + 1 < 32);
        if (has_next)
            pf = reinterpret_cast<const uint4*>(g_w1frag + (kc + 1) * 512)[tid];

        float2 x0 = xrow0[kc * 8 + qp];
        float2 x1 = xrow1[kc * 8 + qp];
        float2 x2 = xrow0[kc * 8 + qp + 4];
        float2 x3 = xrow1[kc * 8 + qp + 4];
        uint32_t a0 = packbf(x0.x, x0.y);
        uint32_t a1 = packbf(x1.x, x1.y);
        uint32_t a2 = packbf(x2.x, x2.y);
        uint32_t a3 = packbf(x3.x, x3.y);

        const uint2* bb = &bsm[buf][lane];
#pragma unroll
        for (int nt = 0; nt < 16; nt++) {
            uint2 b = bb[nt * 32];
            mma16816(acc[nt][0], acc[nt][1], acc[nt][2], acc[nt][3],
                     a0, a1, a2, a3, b.x, b.y);
        }
        if (has_next)
            reinterpret_cast<uint4*>(bsm[buf ^ 1])[tid] = pf;
        __syncthreads();
    }

    uint32_t* out0 = reinterpret_cast<uint32_t*>(g_h1b) + (size_t)(r0 + qrow) * 64;
    uint32_t* out1 = reinterpret_cast<uint32_t*>(g_h1b) + (size_t)(r0 + qrow + 8) * 64;
#pragma unroll
    for (int nt = 0; nt < 16; nt++) {
        out0[nt * 4 + qp] = packbf(acc[nt][0], acc[nt][1]);
        out1[nt * 4 + qp] = packbf(acc[nt][2], acc[nt][3]);
    }

#pragma unroll
    for (int nt = 0; nt < 16; nt++) {
        float s0 = acc[nt][0] + acc[nt][2];
        float s1 = acc[nt][1] + acc[nt][3];
        float q0 = acc[nt][0] * acc[nt][0] + acc[nt][2] * acc[nt][2];
        float q1 = acc[nt][1] * acc[nt][1] + acc[nt][3] * acc[nt][3];
#pragma unroll
        for (int off = 16; off >= 4; off >>= 1) {
            s0 += __shfl_down_sync(0xffffffffu, s0, off);
            s1 += __shfl_down_sync(0xffffffffu, s1, off);
            q0 += __shfl_down_sync(0xffffffffu, q0, off);
            q1 += __shfl_down_sync(0xffffffffu, q1, off);
        }
        if (lane < 4) {
            int c = nt * 8 + lane * 2;
            atomicAdd(&ssum[c],     s0);
            atomicAdd(&ssum[c + 1], s1);
            atomicAdd(&ssq[c],      q0);
            atomicAdd(&ssq[c + 1],  q1);
        }
    }
    __syncthreads();
    if (tid < H) {
        atomicAdd(&g_colsum[tid],   ssum[tid]);
        atomicAdd(&g_colsumsq[tid], ssq[tid]);
    }
}

// ---------------- GEMM2 v2: tensor-core z = relu(bn(h1)) @ W2 + b2 ----------
// warp = 16 rows x 32 cols; block = 8 warps = 128 rows; grid 512.
__global__ void __launch_bounds__(256) k_gemm2(const float* __restrict__ g1,
                                               const float* __restrict__ be1,
                                               const float* __restrict__ B2) {
    __shared__ uint2 w2s[8 * 128];     // 8KB: [kc][nt*32+lane]
    __shared__ float sc[H], sh[H];
    const int tid  = threadIdx.x;
    const int w    = tid >> 5;
    const int lane = tid & 31;
    const int qrow = lane >> 2;
    const int qp   = lane & 3;
    const int r0   = blockIdx.x * 128 + w * 16;

    if (tid < H) {
        float mu  = g_colsum[tid] * (1.0f / N_ROWS);
        float var = g_colsumsq[tid] * (1.0f / N_ROWS) - mu * mu;
        float s   = g1[tid] * rsqrtf(var + BN_EPS);
        sc[tid] = s;
        sh[tid] = be1[tid] - mu * s;
    }
    for (int i = tid; i < 1024; i += 256) w2s[i] = g_w2frag[i];
    __syncthreads();

    // bias-initialized accumulators
    float acc[4][4];
#pragma unroll
    for (int nt = 0; nt < 4; nt++) {
        float2 b2 = *reinterpret_cast<const float2*>(B2 + nt * 8 + qp * 2);
        acc[nt][0] = b2.x; acc[nt][1] = b2.y;
        acc[nt][2] = b2.x; acc[nt][3] = b2.y;
    }

    const uint32_t* h0p = reinterpret_cast<const uint32_t*>(g_h1b) + (size_t)(r0 + qrow) * 64;
    const uint32_t* h1p = reinterpret_cast<const uint32_t*>(g_h1b) + (size_t)(r0 + qrow + 8) * 64;

#pragma unroll
    for (int kc = 0; kc < 8; kc++) {
        const int k0 = kc * 16 + qp * 2;
        float2 sc0 = *reinterpret_cast<const float2*>(sc + k0);
        float2 sh0 = *reinterpret_cast<const float2*>(sh + k0);
        float2 sc1 = *reinterpret_cast<const float2*>(sc + k0 + 8);
        float2 sh1 = *reinterpret_cast<const float2*>(sh + k0 + 8);

        uint32_t u0 = h0p[kc * 8 + qp];
        uint32_t u1 = h1p[kc * 8 + qp];
        uint32_t u2 = h0p[kc * 8 + qp + 4];
        uint32_t u3 = h1p[kc * 8 + qp + 4];

        float2 f0 = __bfloat1622float2(*reinterpret_cast<__nv_bfloat162*>(&u0));
        float2 f1 = __bfloat1622float2(*reinterpret_cast<__nv_bfloat162*>(&u1));
        float2 f2 = __bfloat1622float2(*reinterpret_cast<__nv_bfloat162*>(&u2));
        float2 f3 = __bfloat1622float2(*reinterpret_cast<__nv_bfloat162*>(&u3));

        uint32_t a0 = packbf(fmaxf(fmaf(f0.x, sc0.x, sh0.x), 0.f),
                             fmaxf(fmaf(f0.y, sc0.y, sh0.y), 0.f));
        uint32_t a1 = packbf(fmaxf(fmaf(f1.x, sc0.x, sh0.x), 0.f),
                             fmaxf(fmaf(f1.y, sc0.y, sh0.y), 0.f));
        uint32_t a2 = packbf(fmaxf(fmaf(f2.x, sc1.x, sh1.x), 0.f),
                             fmaxf(fmaf(f2.y, sc1.y, sh1.y), 0.f));
        uint32_t a3 = packbf(fmaxf(fmaf(f3.x, sc1.x, sh1.x), 0.f),
                             fmaxf(fmaf(f3.y, sc1.y, sh1.y), 0.f));

        const uint2* bb = &w2s[kc * 128 + lane];
#pragma unroll
        for (int nt = 0; nt < 4; nt++) {
            uint2 b = bb[nt * 32];
            mma16816(acc[nt][0], acc[nt][1], acc[nt][2], acc[nt][3],
                     a0, a1, a2, a3, b.x, b.y);
        }
    }

    // pack z -> bf16, znorm from rounded values
    uint32_t* z0 = reinterpret_cast<uint32_t*>(g_zb) + (size_t)(r0 + qrow) * 16;
    uint32_t* z1 = reinterpret_cast<uint32_t*>(g_zb) + (size_t)(r0 + qrow + 8) * 16;
    float n0 = 0.f, n1 = 0.f;
#pragma unroll
    for (int nt = 0; nt < 4; nt++) {
        uint32_t p0 = packbf(acc[nt][0], acc[nt][1]);
        uint32_t p1 = packbf(acc[nt][2], acc[nt][3]);
        z0[nt * 4 + qp] = p0;
        z1[nt * 4 + qp] = p1;
        float2 r0f = __bfloat1622float2(*reinterpret_cast<__nv_bfloat162*>(&p0));
        float2 r1f = __bfloat1622float2(*reinterpret_cast<__nv_bfloat162*>(&p1));
        n0 += r0f.x * r0f.x + r0f.y * r0f.y;
        n1 += r1f.x * r1f.x + r1f.y * r1f.y;
    }
#pragma unroll
    for (int o = 1; o <= 2; o <<= 1) {
        n0 += __shfl_xor_sync(0xffffffffu, n0, o);
        n1 += __shfl_xor_sync(0xffffffffu, n1, o);
    }
    if (qp == 0) {
        g_znorm[r0 + qrow]     = n0;
        g_znorm[r0 + qrow + 8] = n1;
    }
}

// ---------------- assign: MMA distances + packed-uint argmin -----------------
__global__ void __launch_bounds__(256) k_assign() {
    extern __shared__ char smraw[];
    uint32_t* cbw = reinterpret_cast<uint32_t*>(smraw);
    float2*  cnorm2 = reinterpret_cast<float2*>(smraw + KCB * 64);

    const int tid  = threadIdx.x;
    const int row0 = blockIdx.x * 256;

    for (int wb = tid * 4; wb < KCB * 16; wb += 256 * 4) {
        uint4 v = *reinterpret_cast<const uint4*>(g_cbb + wb);
        int r = wb >> 4, w0 = wb & 15;
        int base = r << 4, sw = r & 7;
        cbw[base | ((w0 + 0) ^ sw)] = v.x;
        cbw[base | ((w0 + 1) ^ sw)] = v.y;
        cbw[base | ((w0 + 2) ^ sw)] = v.z;
        cbw[base | ((w0 + 3) ^ sw)] = v.w;
    }
    {
        float4 v = reinterpret_cast<const float4*>(g_cnorm)[tid];
        reinterpret_cast<float4*>(cnorm2)[tid] = v;
    }
    __syncthreads();

    const int w    = tid >> 5;
    const int lane = tid & 31;
    const int qrow = lane >> 2;
    const int qp   = lane & 3;

    const int r0 = row0 + w * 32 + qrow;
    const uint32_t* zw = reinterpret_cast<const uint32_t*>(g_zb);
    uint32_t a00 = zw[(size_t)(r0     ) * 16 + qp];
    uint32_t a01 = zw[(size_t)(r0 +  8) * 16 + qp];
    uint32_t a02 = zw[(size_t)(r0     ) * 16 + qp + 4];
    uint32_t a03 = zw[(size_t)(r0 +  8) * 16 + qp + 4];
    uint32_t a04 = zw[(size_t)(r0     ) * 16 + qp + 8];
    uint32_t a05 = zw[(size_t)(r0 +  8) * 16 + qp + 8];
    uint32_t a06 = zw[(size_t)(r0     ) * 16 + qp + 12];
    uint32_t a07 = zw[(size_t)(r0 +  8) * 16 + qp + 12];
    uint32_t a10 = zw[(size_t)(r0 + 16) * 16 + qp];
    uint32_t a11 = zw[(size_t)(r0 + 24) * 16 + qp];
    uint32_t a12 = zw[(size_t)(r0 + 16) * 16 + qp + 4];
    uint32_t a13 = zw[(size_t)(r0 + 24) * 16 + qp + 4];
    uint32_t a14 = zw[(size_t)(r0 + 16) * 16 + qp + 8];
    uint32_t a15 = zw[(size_t)(r0 + 24) * 16 + qp + 8];
    uint32_t a16 = zw[(size_t)(r0 + 16) * 16 + qp + 12];
    uint32_t a17 = zw[(size_t)(r0 + 24) * 16 + qp + 12];

    const float zn0 = g_znorm[r0];
    const float zn1 = g_znorm[r0 + 8];
    const float zn2 = g_znorm[r0 + 16];
    const float zn3 = g_znorm[r0 + 24];

    uint32_t best0 = 0xFFFFFFFFu, best1 = 0xFFFFFFFFu;
    uint32_t best2 = 0xFFFFFFFFu, best3 = 0xFFFFFFFFu;
    const int boff = (qrow << 4) | (qp ^ qrow);

#pragma unroll 2
    for (int nt = 0; nt < KCB / 8; nt++) {
        uint32_t b0 = cbw[nt * 128 + boff];
        uint32_t b1 = cbw[nt * 128 + (boff ^ 4)];
        uint32_t b2 = cbw[nt * 128 + (boff ^ 8)];
        uint32_t b3 = cbw[nt * 128 + (boff ^ 12)];

        float d0 = 0.f, d1 = 0.f, d2 = 0.f, d3 = 0.f;
        float e0 = 0.f, e1 = 0.f, e2 = 0.f, e3 = 0.f;
        mma16816(d0, d1, d2, d3, a00, a01, a02, a03, b0, b1);
        mma16816(d0, d1, d2, d3, a04, a05, a06, a07, b2, b3);
        mma16816(e0, e1, e2, e3, a10, a11, a12, a13, b0, b1);
        mma16816(e0, e1, e2, e3, a14, a15, a16, a17, b2, b3);

        int ncol = nt * 8 + qp * 2;
        float2 cn = cnorm2[nt * 4 + qp];
        uint32_t k00 = (__float_as_uint(fmaf(-2.f, d0, zn0 + cn.x)) & 0xFFFFFC00u) | ncol;
        uint32_t k01 = (__float_as_uint(fmaf(-2.f, d1, zn0 + cn.y)) & 0xFFFFFC00u) | (ncol + 1);
        uint32_t k10 = (__float_as_uint(fmaf(-2.f, d2, zn1 + cn.x)) & 0xFFFFFC00u) | ncol;
        uint32_t k11 = (__float_as_uint(fmaf(-2.f, d3, zn1 + cn.y)) & 0xFFFFFC00u) | (ncol + 1);
        uint32_t k20 = (__float_as_uint(fmaf(-2.f, e0, zn2 + cn.x)) & 0xFFFFFC00u) | ncol;
        uint32_t k21 = (__float_as_uint(fmaf(-2.f, e1, zn2 + cn.y)) & 0xFFFFFC00u) | (ncol + 1);
        uint32_t k30 = (__float_as_uint(fmaf(-2.f, e2, zn3 + cn.x)) & 0xFFFFFC00u) | ncol;
        uint32_t k31 = (__float_as_uint(fmaf(-2.f, e3, zn3 + cn.y)) & 0xFFFFFC00u) | (ncol + 1);
        best0 = min(best0, min(k00, k01));
        best1 = min(best1, min(k10, k11));
        best2 = min(best2, min(k20, k21));
        best3 = min(best3, min(k30, k31));
    }

#pragma unroll
    for (int off = 1; off <= 2; off <<= 1) {
        best0 = min(best0, __shfl_xor_sync(0xffffffffu, best0, off));
        best1 = min(best1, __shfl_xor_sync(0xffffffffu, best1, off));
        best2 = min(best2, __shfl_xor_sync(0xffffffffu, best2, off));
        best3 = min(best3, __shfl_xor_sync(0xffffffffu, best3, off));
    }

    double db = 0.0;
    if (qp == 0) {
        int c0v = best0 & 0x3FF, c1v = best1 & 0x3FF;
        int c2v = best2 & 0x3FF, c3v = best3 & 0x3FF;
        g_topics[r0]      = c0v;
        g_topics[r0 + 8]  = c1v;
        g_topics[r0 + 16] = c2v;
        g_topics[r0 + 24] = c3v;
        atomicAdd(&g_counts[c0v], 1);
        atomicAdd(&g_counts[c1v], 1);
        atomicAdd(&g_counts[c2v], 1);
        atomicAdd(&g_counts[c3v], 1);
        db = (double)__uint_as_float(best0 & 0xFFFFFC00u)
           + (double)__uint_as_float(best1 & 0xFFFFFC00u)
           + (double)__uint_as_float(best2 & 0xFFFFFC00u)
           + (double)__uint_as_float(best3 & 0xFFFFFC00u);
    }
#pragma unroll
    for (int o = 16; o; o >>= 1) db += __shfl_down_sync(0xffffffffu, db, o);
    if (lane == 0) atomicAdd(&g_zcloss, db);
}

// ---------------- decoder proj + fused weighted BN stats ---------------------
__global__ void __launch_bounds__(128) k_decproj(const float* __restrict__ CB,
                                                 const float* __restrict__ W1d) {
    __shared__ float cbs[16 * D];
    __shared__ float w1s[D * H];
    __shared__ float cnt[16];
    const int tid = threadIdx.x;
    const int k0  = blockIdx.x * 16;

    for (int i = tid * 4; i < 16 * D; i += 128 * 4)
        *reinterpret_cast<float4*>(cbs + i) =
            *reinterpret_cast<const float4*>(CB + k0 * D + i);
    for (int i = tid * 4; i < D * H; i += 128 * 4)
        *reinterpret_cast<float4*>(w1s + i) =
            *reinterpret_cast<const float4*>(W1d + i);
    if (tid < 16) cnt[tid] = (float)g_counts[k0 + tid];
    __syncthreads();

    const int h = tid;
    float s = 0.f, ss = 0.f;
#pragma unroll 4
    for (int kk = 0; kk < 16; kk++) {
        float p = 0.f;
#pragma unroll
        for (int d = 0; d < D; d++) p = fmaf(cbs[kk * D + d], w1s[d * H + h], p);
        g_proj[(k0 + kk) * H + h] = p;
        float c = cnt[kk];
        s  = fmaf(c, p, s);
        ss = fmaf(c * p, p, ss);
    }
    atomicAdd(&g_dsum[h], s);
    atomicAdd(&g_dss[h], ss);
}

// ---------------- decoder output ---------------------------------------------
__global__ void __launch_bounds__(256) k_decout(const float* __restrict__ g2,
                                                const float* __restrict__ be2,
                                                const float* __restrict__ W2d,
                                                const float* __restrict__ B2d) {
    __shared__ float hb[4][H];
    __shared__ float sc2[H], sh2[H];
    const int t  = threadIdx.x;
    const int k0 = blockIdx.x * 4;

    if (t < H) {
        float mu  = g_dsum[t] * (1.0f / N_ROWS);
        float var = g_dss[t] * (1.0f / N_ROWS) - mu * mu;
        float s   = g2[t] * rsqrtf(var + BN_EPS);
        sc2[t] = s;
        sh2[t] = be2[t] - mu * s;
    }
    __syncthreads();
    for (int i = t; i < 4 * H; i += 256) {
        int kk = i >> 7, h = i & 127;
        float v = fmaf(g_proj[(k0 + kk) * H + h], sc2[h], sh2[h]);
        hb[kk][h] = fmaxf(v, 0.f);
    }
    __syncthreads();
    for (int o = t; o < DIN; o += 256) {
        float b = B2d[o];
        float s0 = b, s1 = b, s2 = b, s3 = b;
#pragma unroll 4
        for (int h = 0; h < H; h++) {
            float wv = W2d[h * DIN + o];
            s0 = fmaf(hb[0][h], wv, s0);
            s1 = fmaf(hb[1][h], wv, s1);
            s2 = fmaf(hb[2][h], wv, s2);
            s3 = fmaf(hb[3][h], wv, s3);
        }
        g_xrow[(size_t)(k0 + 0) * DIN + o] = s0;
        g_xrow[(size_t)(k0 + 1) * DIN + o] = s1;
        g_xrow[(size_t)(k0 + 2) * DIN + o] = s2;
        g_xrow[(size_t)(k0 + 3) * DIN + o] = s3;
    }
}

// ---------------- recon loss --------------------------------------------------
__global__ void k_recon(const float* __restrict__ X) {
    const int gtid   = blockIdx.x * blockDim.x + threadIdx.x;
    const int gw     = gtid >> 5;
    const int lane   = threadIdx.x & 31;
    const int nwarps = (gridDim.x * blockDim.x) >> 5;
    double dacc = 0.0;
    for (int n = gw; n < N_ROWS; n += nwarps) {
        int tpc = g_topics[n];
        const float4* xr = reinterpret_cast<const float4*>(g_xrow + (size_t)tpc * DIN);
        const float4* xx = reinterpret_cast<const float4*>(X + (size_t)n * DIN);
        float a = 0.f;
#pragma unroll
        for (int q = 0; q < 4; q++) {
            float4 rv = xr[lane + 32 * q];
            float4 xv = xx[lane + 32 * q];
            float e0 = rv.x - xv.x, e1 = rv.y - xv.y;
            float e2 = rv.z - xv.z, e3 = rv.w - xv.w;
            a = fmaf(e0, e0, a); a = fmaf(e1, e1, a);
            a = fmaf(e2, e2, a); a = fmaf(e3, e3, a);
        }
        dacc += (double)a;
    }
#pragma unroll
    for (int o = 16; o; o >>= 1) dacc += __shfl_down_sync(0xffffffffu, dacc, o);
    if (lane == 0) atomicAdd(&g_recon, dacc);
}

__global__ void k_final(float* __restrict__ out) {
    out[0] = (float)(2.0 * g_zcloss + sqrt(g_recon));
}

// ---------------- launch ------------------------------------------------------
extern "C" void kernel_launch(void* const* d_in, const int* in_sizes, int n_in,
                              void* d_out, int out_size) {
    const float* X        = (const float*)d_in[0];
    const float* enc_w1   = (const float*)d_in[1];
    const float* enc_g1   = (const float*)d_in[3];
    const float* enc_be1  = (const float*)d_in[4];
    const float* enc_w2   = (const float*)d_in[5];
    const float* enc_b2   = (const float*)d_in[6];
    const float* dec_w1   = (const float*)d_in[7];
    const float* dec_g1   = (const float*)d_in[9];
    const float* dec_be1  = (const float*)d_in[10];
    const float* dec_w2   = (const float*)d_in[11];
    const float* dec_b2   = (const float*)d_in[12];
    const float* codebook = (const float*)d_in[13];
    float* out = (float*)d_out;

    const int assign_smem = KCB * 64 + KCB * 4;               // 69632
    cudaFuncSetAttribute(k_assign, cudaFuncAttributeMaxDynamicSharedMemorySize, assign_smem);

    k_zero_a <<<4, 256>>>(enc_w2);                            // launch 1
    k_zero_bc<<<8, 256>>>(codebook, enc_w1);                  // launch 2
    k_gemm1  <<<N_ROWS / 128, 256>>>(X);                      // launch 3
    k_gemm2  <<<N_ROWS / 128, 256>>>(enc_g1, enc_be1, enc_b2);// launch 4 (ncu)
    k_assign <<<N_ROWS / 256, 256, assign_smem>>>();
    k_decproj<<<KCB / 16, 128>>>(codebook, dec_w1);
    k_decout <<<KCB / 4, 256>>>(dec_g1, dec_be1, dec_w2, dec_b2);
    k_recon  <<<256, 256>>>(X);
    k_final  <<<1, 1>>>(out);
}